// round 16
// baseline (speedup 1.0000x reference)
#include <cuda_runtime.h>
#include <cuda_bf16.h>

// Wrapped SAT box query, separable inclusion-exclusion form:
//   result[n,c] = sum_{a in Rset} sum_{b in Cset} sgn_a*sgn_b * sat[ia, ib, c]
// Each axis contributes up to 3 (index, sign) terms; dead slots have sign 0.
// i(u)=floor(u*512-0.5) is exact and matches the JAX reference bitwise.
//
// R16: back to the best-performing R11 geometry (4 ch/thread, 72 lanes/point,
// 4 points/block, ~40 regs, high occupancy) + PREDICATED loads. Dead slots
// (weight 0 — expected 2.75 of 9, since each axis wraps with p~0.5) previously
// still issued LDG.128s into L2-hot row 0, wasting ~30% of L1/L2 sector
// bandwidth, which is the binding resource (L2 delivers ~1.36 GB/launch vs
// 615 MB DRAM). Predicate is warp-uniform per point -> @P LDG, no divergence;
// loads remain a single batched independent group so MLP is unchanged.

#define HDIM 512
#define WDIM 512

__device__ __forceinline__ int sat_index(float u) {
    // floor(u * 512 - 0.5), exact
    return (int)floorf(__fsub_rn(__fmul_rn(u, 512.0f), 0.5f));
}

__global__ void sat_query_v4p_kernel(
    const float* __restrict__ sat,
    const float* __restrict__ x,
    const int*   __restrict__ p_start,
    float*       __restrict__ out,
    int C, int C_out, int N)
{
    const int n = blockIdx.x * blockDim.y + threadIdx.y;
    if (n >= N) return;

    int s0 = *p_start;              // uniform, L1-hot; hoisted to overlap setup
    if (s0 < 0) s0 = 0;

    // ---- per-point scalar setup (redundant across 72 lanes; cheap) ----
    const float4 q = __ldg(reinterpret_cast<const float4*>(x) + n);
    float cu = q.x, cv = q.y, du = q.z, dv = q.w;

    float hu = __fmul_rn(du, 0.5f);
    float hv = __fmul_rn(dv, 0.5f);
    float su = __fsub_rn(cu, hu), eu = __fadd_rn(cu, hu);
    float sv = __fsub_rn(cv, hv), ev = __fadd_rn(cv, hv);

    if (du < 0.0f) { float t = su; su = eu; eu = t; }
    if (dv < 0.0f) { float t = sv; sv = ev; ev = t; }

    su = __fsub_rn(su, floorf(su)); eu = __fsub_rn(eu, floorf(eu));
    sv = __fsub_rn(sv, floorf(sv)); ev = __fsub_rn(ev, floorf(ev));

    // ---- per-axis inclusion-exclusion lists (3 slots, dead slot => sign 0) ----
    int   iu_e = sat_index(eu);
    int   iu_s = sat_index(su) - 1;
    bool  wu   = (su > eu);
    int   rI0 = (iu_e >= 0) ? iu_e : 0;  float rS0 = (iu_e >= 0) ? 1.0f : 0.0f;
    int   rI1 = wu ? (HDIM - 1) : 0;     float rS1 = wu ? 1.0f : 0.0f;
    int   rI2 = (iu_s >= 0) ? iu_s : 0;  float rS2 = (iu_s >= 0) ? -1.0f : 0.0f;

    int   iv_e = sat_index(ev);
    int   iv_s = sat_index(sv) - 1;
    bool  wv   = (sv > ev);
    int   cI0 = (iv_e >= 0) ? iv_e : 0;  float cS0 = (iv_e >= 0) ? 1.0f : 0.0f;
    int   cI1 = wv ? (WDIM - 1) : 0;     float cS1 = wv ? 1.0f : 0.0f;
    int   cI2 = (iv_s >= 0) ? iv_s : 0;  float cS2 = (iv_s >= 0) ? -1.0f : 0.0f;

    const int WC = WDIM * C;
    int r0 = rI0 * WC, r1 = rI1 * WC, r2 = rI2 * WC;
    int c0 = cI0 * C,  c1 = cI1 * C,  c2 = cI2 * C;

    int   o[9];
    float w[9];
    o[0] = r0 + c0; o[1] = r0 + c1; o[2] = r0 + c2;
    o[3] = r1 + c0; o[4] = r1 + c1; o[5] = r1 + c2;
    o[6] = r2 + c0; o[7] = r2 + c1; o[8] = r2 + c2;
    w[0] = rS0 * cS0; w[1] = rS0 * cS1; w[2] = rS0 * cS2;
    w[3] = rS1 * cS0; w[4] = rS1 * cS1; w[5] = rS1 * cS2;
    w[6] = rS2 * cS0; w[7] = rS2 * cS1; w[8] = rS2 * cS2;

    const float* __restrict__ satc = sat + s0;
    const size_t obase = (size_t)n * (size_t)C_out;

    const int ch = threadIdx.x * 4;
    if (ch >= C_out) return;

    const bool aligned = ((C & 3) == 0) && ((s0 & 3) == 0) && (ch + 4 <= C_out);

    if (aligned) {
        // ---- fast path: up to 9 PREDICATED independent LDG.128 ----
        const float4* __restrict__ p = reinterpret_cast<const float4*>(satc + ch);
        const float4 z4 = make_float4(0.0f, 0.0f, 0.0f, 0.0f);
        float4 v[9];
        #pragma unroll
        for (int s = 0; s < 9; s++) {
            // warp-uniform predicate (per point); dead slot -> skip the load
            v[s] = (w[s] != 0.0f) ? __ldg(p + (o[s] >> 2)) : z4;
        }

        // 3 independent chains per component, then combine
        float ax = __fmul_rn(w[0], v[0].x), bx = __fmul_rn(w[1], v[1].x), dx = __fmul_rn(w[2], v[2].x);
        float ay = __fmul_rn(w[0], v[0].y), by = __fmul_rn(w[1], v[1].y), dy = __fmul_rn(w[2], v[2].y);
        float az = __fmul_rn(w[0], v[0].z), bz = __fmul_rn(w[1], v[1].z), dz = __fmul_rn(w[2], v[2].z);
        float aw = __fmul_rn(w[0], v[0].w), bw = __fmul_rn(w[1], v[1].w), dw = __fmul_rn(w[2], v[2].w);

        ax = fmaf(w[3], v[3].x, ax); bx = fmaf(w[4], v[4].x, bx); dx = fmaf(w[5], v[5].x, dx);
        ay = fmaf(w[3], v[3].y, ay); by = fmaf(w[4], v[4].y, by); dy = fmaf(w[5], v[5].y, dy);
        az = fmaf(w[3], v[3].z, az); bz = fmaf(w[4], v[4].z, bz); dz = fmaf(w[5], v[5].z, dz);
        aw = fmaf(w[3], v[3].w, aw); bw = fmaf(w[4], v[4].w, bw); dw = fmaf(w[5], v[5].w, dw);

        ax = fmaf(w[6], v[6].x, ax); bx = fmaf(w[7], v[7].x, bx); dx = fmaf(w[8], v[8].x, dx);
        ay = fmaf(w[6], v[6].y, ay); by = fmaf(w[7], v[7].y, by); dy = fmaf(w[8], v[8].y, dy);
        az = fmaf(w[6], v[6].z, az); bz = fmaf(w[7], v[7].z, bz); dz = fmaf(w[8], v[8].z, dz);
        aw = fmaf(w[6], v[6].w, aw); bw = fmaf(w[7], v[7].w, bw); dw = fmaf(w[8], v[8].w, dw);

        float4 r;
        r.x = __fadd_rn(__fadd_rn(ax, bx), dx);
        r.y = __fadd_rn(__fadd_rn(ay, by), dy);
        r.z = __fadd_rn(__fadd_rn(az, bz), dz);
        r.w = __fadd_rn(__fadd_rn(aw, bw), dw);

        *reinterpret_cast<float4*>(out + obase + ch) = r;
    } else {
        // ---- generic scalar path (sliced / unaligned / tail channels) ----
        #pragma unroll
        for (int k = 0; k < 4; k++) {
            int c = ch + k;
            if (c >= C_out) break;
            float acc = 0.0f;
            #pragma unroll
            for (int s = 0; s < 9; s++) {
                float vv = (w[s] != 0.0f) ? satc[o[s] + c] : 0.0f;
                acc = fmaf(w[s], vv, acc);
            }
            out[obase + c] = acc;
        }
    }
}

extern "C" void kernel_launch(void* const* d_in, const int* in_sizes, int n_in,
                              void* d_out, int out_size) {
    const float* sat   = (const float*)d_in[0];
    const float* x     = (const float*)d_in[1];
    const int*   start = (const int*)d_in[2];

    const int N     = in_sizes[1] / 4;
    const int C     = in_sizes[0] / (HDIM * WDIM);
    const int C_out = out_size / N;

    int lanes = (C_out + 3) / 4;          // float4 lanes per point (72 for C=288)
    if (lanes < 1) lanes = 1;
    if (lanes > 1024) lanes = 1024;

    int ppb = 1024 / lanes;               // points per block
    if (ppb > 4) ppb = 4;
    if (ppb < 1) ppb = 1;

    dim3 bd(lanes, ppb);
    int grid = (N + ppb - 1) / ppb;

    sat_query_v4p_kernel<<<grid, bd>>>(sat, x, start, (float*)d_out, C, C_out, N);
}

// round 17
// speedup vs baseline: 1.2735x; 1.2735x over previous
#include <cuda_runtime.h>
#include <cuda_bf16.h>

// Wrapped SAT box query, separable inclusion-exclusion form:
//   result[n,c] = sum_{a in Rset} sum_{b in Cset} sgn_a*sgn_b * sat[ia, ib, c]
// Each axis contributes up to 3 (index, sign) terms; dead slots get sign 0 and
// index 0 (loads stay unpredicated — R16 showed they're cache-hot and free).
// i(u)=floor(u*512-0.5) is exact and matches the JAX reference bitwise.
//
// R17: persistent grid-stride kernel with the R11 body (4 ch/thread, 72 lanes
// per point, 4 point-streams per block). R11's 32768 one-shot CTAs cost ~32
// waves of CTA churn (~2360 cyc each per the T_chip model) and exposed the
// full ldx->setup->9xldg->stg chain once per point. The persistent loop
// removes wave transitions and prefetches the next point's coords so setup
// overlaps the current point's memory wait.

#define HDIM 512
#define WDIM 512

__device__ __forceinline__ int sat_index(float u) {
    // floor(u * 512 - 0.5), exact
    return (int)floorf(__fsub_rn(__fmul_rn(u, 512.0f), 0.5f));
}

__global__ void __launch_bounds__(288) sat_query_pers_kernel(
    const float* __restrict__ sat,
    const float* __restrict__ x,
    const int*   __restrict__ p_start,
    float*       __restrict__ out,
    int C, int C_out, int N)
{
    int s0 = *p_start;              // uniform, L1-hot
    if (s0 < 0) s0 = 0;
    const float* __restrict__ satc = sat + s0;

    const int ch = threadIdx.x * 4;
    if (ch >= C_out) return;
    const bool aligned = ((C & 3) == 0) && ((s0 & 3) == 0) && (ch + 4 <= C_out);

    const int WC = WDIM * C;
    const float4* __restrict__ x4 = reinterpret_cast<const float4*>(x);

    const int stride = gridDim.x * blockDim.y;
    int n = blockIdx.x * blockDim.y + threadIdx.y;
    if (n >= N) return;

    float4 q = __ldg(x4 + n);

    for (; n < N; n += stride) {
        // ---- prefetch next point's coords (overlaps this point's mem wait) ----
        int n_next = n + stride;
        float4 q_next = (n_next < N) ? __ldg(x4 + n_next) : q;

        // ---- per-point scalar setup ----
        float cu = q.x, cv = q.y, du = q.z, dv = q.w;

        float hu = __fmul_rn(du, 0.5f);
        float hv = __fmul_rn(dv, 0.5f);
        float su = __fsub_rn(cu, hu), eu = __fadd_rn(cu, hu);
        float sv = __fsub_rn(cv, hv), ev = __fadd_rn(cv, hv);

        if (du < 0.0f) { float t = su; su = eu; eu = t; }
        if (dv < 0.0f) { float t = sv; sv = ev; ev = t; }

        su = __fsub_rn(su, floorf(su)); eu = __fsub_rn(eu, floorf(eu));
        sv = __fsub_rn(sv, floorf(sv)); ev = __fsub_rn(ev, floorf(ev));

        // ---- per-axis inclusion-exclusion lists (dead slot => sign 0) ----
        int   iu_e = sat_index(eu);
        int   iu_s = sat_index(su) - 1;
        bool  wu   = (su > eu);
        int   rI0 = (iu_e >= 0) ? iu_e : 0;  float rS0 = (iu_e >= 0) ? 1.0f : 0.0f;
        int   rI1 = wu ? (HDIM - 1) : 0;     float rS1 = wu ? 1.0f : 0.0f;
        int   rI2 = (iu_s >= 0) ? iu_s : 0;  float rS2 = (iu_s >= 0) ? -1.0f : 0.0f;

        int   iv_e = sat_index(ev);
        int   iv_s = sat_index(sv) - 1;
        bool  wv   = (sv > ev);
        int   cI0 = (iv_e >= 0) ? iv_e : 0;  float cS0 = (iv_e >= 0) ? 1.0f : 0.0f;
        int   cI1 = wv ? (WDIM - 1) : 0;     float cS1 = wv ? 1.0f : 0.0f;
        int   cI2 = (iv_s >= 0) ? iv_s : 0;  float cS2 = (iv_s >= 0) ? -1.0f : 0.0f;

        int r0 = rI0 * WC, r1 = rI1 * WC, r2 = rI2 * WC;
        int c0 = cI0 * C,  c1 = cI1 * C,  c2 = cI2 * C;

        const int o00 = r0 + c0, o01 = r0 + c1, o02 = r0 + c2;
        const int o10 = r1 + c0, o11 = r1 + c1, o12 = r1 + c2;
        const int o20 = r2 + c0, o21 = r2 + c1, o22 = r2 + c2;
        const float w00 = rS0 * cS0, w01 = rS0 * cS1, w02 = rS0 * cS2;
        const float w10 = rS1 * cS0, w11 = rS1 * cS1, w12 = rS1 * cS2;
        const float w20 = rS2 * cS0, w21 = rS2 * cS1, w22 = rS2 * cS2;

        const size_t obase = (size_t)n * (size_t)C_out;

        if (aligned) {
            // ---- 9 independent LDG.128, 3 independent FMA chains ----
            const float4* __restrict__ p = reinterpret_cast<const float4*>(satc + ch);
            float4 v00 = __ldg(p + (o00 >> 2));
            float4 v01 = __ldg(p + (o01 >> 2));
            float4 v02 = __ldg(p + (o02 >> 2));
            float4 v10 = __ldg(p + (o10 >> 2));
            float4 v11 = __ldg(p + (o11 >> 2));
            float4 v12 = __ldg(p + (o12 >> 2));
            float4 v20 = __ldg(p + (o20 >> 2));
            float4 v21 = __ldg(p + (o21 >> 2));
            float4 v22 = __ldg(p + (o22 >> 2));

            float4 a, b, d;
            a.x = __fmul_rn(w00, v00.x); b.x = __fmul_rn(w01, v01.x); d.x = __fmul_rn(w02, v02.x);
            a.y = __fmul_rn(w00, v00.y); b.y = __fmul_rn(w01, v01.y); d.y = __fmul_rn(w02, v02.y);
            a.z = __fmul_rn(w00, v00.z); b.z = __fmul_rn(w01, v01.z); d.z = __fmul_rn(w02, v02.z);
            a.w = __fmul_rn(w00, v00.w); b.w = __fmul_rn(w01, v01.w); d.w = __fmul_rn(w02, v02.w);

            a.x = fmaf(w10, v10.x, a.x); b.x = fmaf(w11, v11.x, b.x); d.x = fmaf(w12, v12.x, d.x);
            a.y = fmaf(w10, v10.y, a.y); b.y = fmaf(w11, v11.y, b.y); d.y = fmaf(w12, v12.y, d.y);
            a.z = fmaf(w10, v10.z, a.z); b.z = fmaf(w11, v11.z, b.z); d.z = fmaf(w12, v12.z, d.z);
            a.w = fmaf(w10, v10.w, a.w); b.w = fmaf(w11, v11.w, b.w); d.w = fmaf(w12, v12.w, d.w);

            a.x = fmaf(w20, v20.x, a.x); b.x = fmaf(w21, v21.x, b.x); d.x = fmaf(w22, v22.x, d.x);
            a.y = fmaf(w20, v20.y, a.y); b.y = fmaf(w21, v21.y, b.y); d.y = fmaf(w22, v22.y, d.y);
            a.z = fmaf(w20, v20.z, a.z); b.z = fmaf(w21, v21.z, b.z); d.z = fmaf(w22, v22.z, d.z);
            a.w = fmaf(w20, v20.w, a.w); b.w = fmaf(w21, v21.w, b.w); d.w = fmaf(w22, v22.w, d.w);

            float4 r;
            r.x = __fadd_rn(__fadd_rn(a.x, b.x), d.x);
            r.y = __fadd_rn(__fadd_rn(a.y, b.y), d.y);
            r.z = __fadd_rn(__fadd_rn(a.z, b.z), d.z);
            r.w = __fadd_rn(__fadd_rn(a.w, b.w), d.w);

            *reinterpret_cast<float4*>(out + obase + ch) = r;
        } else {
            // ---- generic scalar path (sliced / unaligned / tail channels) ----
            #pragma unroll
            for (int k = 0; k < 4; k++) {
                int c = ch + k;
                if (c >= C_out) break;
                float acc;
                acc = __fmul_rn(w00, satc[o00 + c]);
                acc = fmaf(w01, satc[o01 + c], acc);
                acc = fmaf(w02, satc[o02 + c], acc);
                acc = fmaf(w10, satc[o10 + c], acc);
                acc = fmaf(w11, satc[o11 + c], acc);
                acc = fmaf(w12, satc[o12 + c], acc);
                acc = fmaf(w20, satc[o20 + c], acc);
                acc = fmaf(w21, satc[o21 + c], acc);
                acc = fmaf(w22, satc[o22 + c], acc);
                out[obase + c] = acc;
            }
        }

        q = q_next;
    }
}

extern "C" void kernel_launch(void* const* d_in, const int* in_sizes, int n_in,
                              void* d_out, int out_size) {
    const float* sat   = (const float*)d_in[0];
    const float* x     = (const float*)d_in[1];
    const int*   start = (const int*)d_in[2];

    const int N     = in_sizes[1] / 4;
    const int C     = in_sizes[0] / (HDIM * WDIM);
    const int C_out = out_size / N;

    int lanes = (C_out + 3) / 4;          // float4 lanes per point (72 for C=288)
    if (lanes < 1) lanes = 1;
    if (lanes > 1024) lanes = 1024;
    int ppb = 1024 / lanes;               // point-streams per block
    if (ppb > 4) ppb = 4;
    if (ppb < 1) ppb = 1;
    dim3 bd(lanes, ppb);
    const int tpb = lanes * ppb;

    // exactly one resident wave: SMs x max-blocks-per-SM (host-side queries,
    // graph-capture safe: no stream ops, no allocation)
    int dev = 0, nsm = 148, bpsm = 4;
    cudaGetDevice(&dev);
    cudaDeviceGetAttribute(&nsm, cudaDevAttrMultiProcessorCount, dev);
    cudaOccupancyMaxActiveBlocksPerMultiprocessor(&bpsm, sat_query_pers_kernel, tpb, 0);
    if (bpsm < 1) bpsm = 1;

    int grid = nsm * bpsm;
    int max_grid = (N + ppb - 1) / ppb;   // never more streams than points
    if (grid > max_grid) grid = max_grid;
    if (grid < 1) grid = 1;

    sat_query_pers_kernel<<<grid, bd>>>(sat, x, start, (float*)d_out, C, C_out, N);
}